// round 14
// baseline (speedup 1.0000x reference)
#include <cuda_runtime.h>
#include <mma.h>
#include <cstdint>

using namespace nvcuda;

#define MAX_NODES 100000
#define BUCKET 96

// ---------------------------------------------------------------------------
// Scratch (__device__ globals; no allocation allowed)
// ---------------------------------------------------------------------------
__device__ float g_agg0[(size_t)MAX_NODES * 128];
__device__ float g_h[(size_t)MAX_NODES * 128];
__device__ float g_t[(size_t)MAX_NODES * 64];
__device__ float g_pout[(size_t)MAX_NODES * 64];
__device__ float g_WT0[128 * 256];   // [n][k], tf32-rounded: k<128 Wself0^T, k>=128 Wneigh0^T
__device__ float g_WT1[128 * 128];   // tf32-rounded: rows 0-63 Wneigh1^T, rows 64-127 Wself1^T
__device__ int g_cnt[MAX_NODES];
__device__ int g_bucket[(size_t)MAX_NODES * BUCKET];

// ---------------------------------------------------------------------------
// helpers
// ---------------------------------------------------------------------------
__device__ __forceinline__ void cp16(void* smem_dst, const void* gsrc) {
    uint32_t d = (uint32_t)__cvta_generic_to_shared(smem_dst);
    asm volatile("cp.async.ca.shared.global [%0], [%1], 16;" :: "r"(d), "l"(gsrc));
}
__device__ __forceinline__ void cp_commit() {
    asm volatile("cp.async.commit_group;");
}
__device__ __forceinline__ float to_tf32(float x) {
    float r;
    asm("cvt.rna.tf32.f32 %0, %1;" : "=f"(r) : "f"(x));
    return r;
}

// ---------------------------------------------------------------------------
// Bucketed CSR
// ---------------------------------------------------------------------------
__global__ void fill_bucket(const int* __restrict__ src, const int* __restrict__ dst,
                            int n_edges) {
    int e = blockIdx.x * blockDim.x + threadIdx.x;
    if (e < n_edges) {
        int d = dst[e];
        int pos = atomicAdd(&g_cnt[d], 1);
        if (pos < BUCKET) g_bucket[(size_t)d * BUCKET + pos] = src[e];
    }
}

// ---------------------------------------------------------------------------
// Bucket mean-aggregation (width 128) -> agg0 (tf32-rounded).
// One warp per node; 8 independent gathers in flight for latency cover.
// ---------------------------------------------------------------------------
__global__ void agg128_kernel(const float* __restrict__ x, float* __restrict__ out,
                              int n_nodes) {
    int node = (blockIdx.x * blockDim.x + threadIdx.x) >> 5;
    if (node >= n_nodes) return;
    const int lane = threadIdx.x & 31;
    const int deg = g_cnt[node];
    const int cnt = min(deg, BUCKET);
    const int* __restrict__ b = g_bucket + (size_t)node * BUCKET;
    const float inv = 1.0f / (float)max(deg, 1);

    float4 a[8];
#pragma unroll
    for (int u = 0; u < 8; u++) a[u] = make_float4(0.f, 0.f, 0.f, 0.f);

    int e = 0;
    for (; e + 7 < cnt; e += 8) {
        int s[8];
#pragma unroll
        for (int u = 0; u < 8; u++) s[u] = __ldg(b + e + u);
        float4 v[8];
#pragma unroll
        for (int u = 0; u < 8; u++)
            v[u] = __ldg((const float4*)(x + (size_t)s[u] * 128 + lane * 4));
#pragma unroll
        for (int u = 0; u < 8; u++) {
            a[u].x += v[u].x; a[u].y += v[u].y; a[u].z += v[u].z; a[u].w += v[u].w;
        }
    }
    for (; e + 3 < cnt; e += 4) {
        int s[4];
#pragma unroll
        for (int u = 0; u < 4; u++) s[u] = __ldg(b + e + u);
#pragma unroll
        for (int u = 0; u < 4; u++) {
            float4 v = __ldg((const float4*)(x + (size_t)s[u] * 128 + lane * 4));
            a[u].x += v.x; a[u].y += v.y; a[u].z += v.z; a[u].w += v.w;
        }
    }
    for (; e < cnt; e++) {
        int s0 = __ldg(b + e);
        float4 v = __ldg((const float4*)(x + (size_t)s0 * 128 + lane * 4));
        a[0].x += v.x; a[0].y += v.y; a[0].z += v.z; a[0].w += v.w;
    }
#pragma unroll
    for (int u = 4; u < 8; u++) {
        a[u - 4].x += a[u].x; a[u - 4].y += a[u].y;
        a[u - 4].z += a[u].z; a[u - 4].w += a[u].w;
    }
    float4 r;
    r.x = to_tf32((a[0].x + a[1].x + a[2].x + a[3].x) * inv);
    r.y = to_tf32((a[0].y + a[1].y + a[2].y + a[3].y) * inv);
    r.z = to_tf32((a[0].z + a[1].z + a[2].z + a[3].z) * inv);
    r.w = to_tf32((a[0].w + a[1].w + a[2].w + a[3].w) * inv);
    *reinterpret_cast<float4*>(out + (size_t)node * 128 + lane * 4) = r;
}

// ---------------------------------------------------------------------------
// Final fused aggregation (width 64): out = pout + mean(t[nbrs]); 8-deep MLP
// ---------------------------------------------------------------------------
__global__ void agg64_final(const float* __restrict__ t, const float* __restrict__ pout,
                            float* __restrict__ out, int n_nodes) {
    int node = (blockIdx.x * blockDim.x + threadIdx.x) >> 5;
    if (node >= n_nodes) return;
    const int lane = threadIdx.x & 31;
    const int deg = g_cnt[node];
    const int cnt = min(deg, BUCKET);
    const int* __restrict__ b = g_bucket + (size_t)node * BUCKET;
    const float inv = 1.0f / (float)max(deg, 1);

    float2 a[8];
#pragma unroll
    for (int u = 0; u < 8; u++) a[u] = make_float2(0.f, 0.f);

    int e = 0;
    for (; e + 7 < cnt; e += 8) {
        int s[8];
#pragma unroll
        for (int u = 0; u < 8; u++) s[u] = __ldg(b + e + u);
        float2 v[8];
#pragma unroll
        for (int u = 0; u < 8; u++)
            v[u] = __ldg((const float2*)(t + (size_t)s[u] * 64 + lane * 2));
#pragma unroll
        for (int u = 0; u < 8; u++) { a[u].x += v[u].x; a[u].y += v[u].y; }
    }
    for (; e + 3 < cnt; e += 4) {
        int s[4];
#pragma unroll
        for (int u = 0; u < 4; u++) s[u] = __ldg(b + e + u);
#pragma unroll
        for (int u = 0; u < 4; u++) {
            float2 v = __ldg((const float2*)(t + (size_t)s[u] * 64 + lane * 2));
            a[u].x += v.x; a[u].y += v.y;
        }
    }
    for (; e < cnt; e++) {
        int s0 = __ldg(b + e);
        float2 v = __ldg((const float2*)(t + (size_t)s0 * 64 + lane * 2));
        a[0].x += v.x; a[0].y += v.y;
    }
#pragma unroll
    for (int u = 4; u < 8; u++) { a[u - 4].x += a[u].x; a[u - 4].y += a[u].y; }
    float2 p = __ldg((const float2*)(pout + (size_t)node * 64 + lane * 2));
    float2 r;
    r.x = p.x + (a[0].x + a[1].x + a[2].x + a[3].x) * inv;
    r.y = p.y + (a[0].y + a[1].y + a[2].y + a[3].y) * inv;
    *reinterpret_cast<float2*>(out + (size_t)node * 64 + lane * 2) = r;
}

// ---------------------------------------------------------------------------
// Fused weight transpose, tf32-rounded at source
// ---------------------------------------------------------------------------
__global__ void transpose_all(const float* __restrict__ Wself0,
                              const float* __restrict__ Wneigh0,
                              const float* __restrict__ Wneigh1,
                              const float* __restrict__ Wself1) {
    int i = blockIdx.x * blockDim.x + threadIdx.x;
    if (i < 16384) {
        int k = i >> 7, n = i & 127;
        g_WT0[n * 256 + k] = to_tf32(Wself0[i]);
        g_WT0[n * 256 + 128 + k] = to_tf32(Wneigh0[i]);
    } else {
        i -= 16384;
        if (i < 8192) {
            int k = i >> 6, n = i & 63;
            g_WT1[n * 128 + k] = to_tf32(Wneigh1[i]);
            g_WT1[(64 + n) * 128 + k] = to_tf32(Wself1[i]);
        }
    }
}

// ---------------------------------------------------------------------------
// Shared GEMM core: 256 threads, 8 warps (MW=2 x NW=4), per-warp FM=4 x FN=2.
// BM=128, BN=128. 2 CTAs/SM (<=128 regs, 73.7KB smem).
// MODE 0: h = relu(X@WT0 + Agg@WT0[:,128:] + b)  KTOTAL=256, two A sources
// MODE 1: [t | pout] = X@WT1 (+bias on cols>=64)  KTOTAL=128
// ---------------------------------------------------------------------------
template <int KTOTAL, int MODE>
__global__ void __launch_bounds__(256, 2) gemm_core(
    const float* __restrict__ X, const float* __restrict__ Agg,
    const float* __restrict__ WT, const float* __restrict__ bias,
    float* __restrict__ out0, float* __restrict__ out1, int n_nodes)
{
    constexpr int BM = 128, BN = 128, NCHUNK = KTOTAL / 32;
    constexpr int MW = 2, RM = 64, CN = 32;
    constexpr int FM = 4, FN = 2;
    constexpr int LDS = 36;

    extern __shared__ float smem[];
    float* Xs = smem;                    // 2*128*36 = 9216
    float* Ws = smem + 9216;             // 2*128*36 = 9216  -> 73728 B total
    float* Sbuf = Xs;                    // epilogue staging aliases Xs (dead)

    const int tid = threadIdx.x;
    const int wid = tid >> 5;
    const int lane = tid & 31;
    const int wr = wid % MW;
    const int wc = wid / MW;
    const int block_m = blockIdx.x * BM;

    wmma::fragment<wmma::accumulator, 16, 16, 8, float> acc[FM][FN];
#pragma unroll
    for (int i = 0; i < FM; i++)
#pragma unroll
        for (int j = 0; j < FN; j++) wmma::fill_fragment(acc[i][j], 0.0f);

    auto issue_chunk = [&](int c) {
        const float* __restrict__ srcX = (MODE == 0 && c >= 4) ? Agg : X;
        const int kcol = (MODE == 0) ? (c & 3) * 32 : c * 32;
        float* xbuf = Xs + (c & 1) * BM * LDS;
#pragma unroll
        for (int i = tid; i < BM * 8; i += 256) {
            int m = i >> 3, kq = i & 7;
            int node = min(block_m + m, n_nodes - 1);
            cp16(&xbuf[m * LDS + kq * 4], srcX + (size_t)node * 128 + kcol + kq * 4);
        }
        float* wbuf = Ws + (c & 1) * BN * LDS;
#pragma unroll
        for (int i = tid; i < BN * 8; i += 256) {
            int n = i >> 3, kq = i & 7;
            cp16(&wbuf[n * LDS + kq * 4], WT + (size_t)n * KTOTAL + c * 32 + kq * 4);
        }
        cp_commit();
    };

    issue_chunk(0);

    for (int c = 0; c < NCHUNK; ++c) {
        if (c + 1 < NCHUNK) {
            issue_chunk(c + 1);
            asm volatile("cp.async.wait_group 1;");
        } else {
            asm volatile("cp.async.wait_group 0;");
        }
        __syncthreads();

        const float* xbuf = Xs + (c & 1) * BM * LDS;
        const float* wbuf = Ws + (c & 1) * BN * LDS;

#pragma unroll
        for (int k0 = 0; k0 < 32; k0 += 8) {
            wmma::fragment<wmma::matrix_a, 16, 16, 8, wmma::precision::tf32, wmma::row_major> af[FM];
            wmma::fragment<wmma::matrix_b, 16, 16, 8, wmma::precision::tf32, wmma::col_major> bf[FN];
#pragma unroll
            for (int i = 0; i < FM; i++)
                wmma::load_matrix_sync(af[i], &xbuf[(wr * RM + i * 16) * LDS + k0], LDS);
#pragma unroll
            for (int j = 0; j < FN; j++)
                wmma::load_matrix_sync(bf[j], &wbuf[(wc * CN + j * 16) * LDS + k0], LDS);
#pragma unroll
            for (int i = 0; i < FM; i++)
#pragma unroll
                for (int j = 0; j < FN; j++)
                    wmma::mma_sync(acc[i][j], af[i], bf[j], acc[i][j]);
        }
        __syncthreads();
    }

    // Epilogue
    float* buf = &Sbuf[wid * 256];
#pragma unroll
    for (int i = 0; i < FM; i++) {
#pragma unroll
        for (int j = 0; j < FN; j++) {
            wmma::store_matrix_sync(buf, acc[i][j], 16, wmma::mem_row_major);
            __syncwarp();
            const int r = lane >> 1;
            const int c0 = (lane & 1) * 8;
            const int node = block_m + wr * RM + i * 16 + r;
            const int gcol = wc * CN + j * 16 + c0;
            if (node < n_nodes) {
#pragma unroll
                for (int q = 0; q < 8; q += 4) {
                    float4 v = *reinterpret_cast<const float4*>(&buf[r * 16 + c0 + q]);
                    int n = gcol + q;
                    if (MODE == 0) {
                        float4 bb = *reinterpret_cast<const float4*>(bias + n);
                        v.x = to_tf32(fmaxf(v.x + bb.x, 0.f));
                        v.y = to_tf32(fmaxf(v.y + bb.y, 0.f));
                        v.z = to_tf32(fmaxf(v.z + bb.z, 0.f));
                        v.w = to_tf32(fmaxf(v.w + bb.w, 0.f));
                        *reinterpret_cast<float4*>(out0 + (size_t)node * 128 + n) = v;
                    } else {
                        if (n < 64) {
                            *reinterpret_cast<float4*>(out0 + (size_t)node * 64 + n) = v;
                        } else {
                            int n2 = n - 64;
                            float4 bb = *reinterpret_cast<const float4*>(bias + n2);
                            v.x += bb.x; v.y += bb.y; v.z += bb.z; v.w += bb.w;
                            *reinterpret_cast<float4*>(out1 + (size_t)node * 64 + n2) = v;
                        }
                    }
                }
            }
            __syncwarp();
        }
    }
}

// ---------------------------------------------------------------------------
// Launch (single stream — fork/join regressed in R13)
// ---------------------------------------------------------------------------
extern "C" void kernel_launch(void* const* d_in, const int* in_sizes, int n_in,
                              void* d_out, int out_size) {
    const float* features = (const float*)d_in[0];
    const int*   src      = (const int*)d_in[1];
    const int*   dst      = (const int*)d_in[2];
    const float* Wself0   = (const float*)d_in[3];
    const float* Wneigh0  = (const float*)d_in[4];
    const float* b0       = (const float*)d_in[5];
    const float* Wself1   = (const float*)d_in[6];
    const float* Wneigh1  = (const float*)d_in[7];
    const float* b1       = (const float*)d_in[8];

    const int n_nodes = in_sizes[0] / 128;
    const int n_edges = in_sizes[1];

    float *agg0, *h, *t, *pout, *WT0, *WT1;
    int* cnt;
    cudaGetSymbolAddress((void**)&agg0, g_agg0);
    cudaGetSymbolAddress((void**)&h, g_h);
    cudaGetSymbolAddress((void**)&t, g_t);
    cudaGetSymbolAddress((void**)&pout, g_pout);
    cudaGetSymbolAddress((void**)&WT0, g_WT0);
    cudaGetSymbolAddress((void**)&WT1, g_WT1);
    cudaGetSymbolAddress((void**)&cnt, g_cnt);

    const int smem_core = 18432 * 4;  // 73728 B -> 2 CTAs/SM
    static bool attr_set = false;
    if (!attr_set) {
        cudaFuncSetAttribute((const void*)gemm_core<256, 0>,
                             cudaFuncAttributeMaxDynamicSharedMemorySize, smem_core);
        cudaFuncSetAttribute((const void*)gemm_core<128, 1>,
                             cudaFuncAttributeMaxDynamicSharedMemorySize, smem_core);
        attr_set = true;
    }

    cudaMemsetAsync(cnt, 0, sizeof(int) * (size_t)n_nodes, 0);

    transpose_all<<<(24576 + 255) / 256, 256>>>(Wself0, Wneigh0, Wneigh1, Wself1);
    fill_bucket<<<(n_edges + 511) / 512, 512>>>(src, dst, n_edges);

    const int gblocks = (n_nodes + 127) / 128;
    const int ablocks = (int)(((long long)n_nodes * 32 + 255) / 256);

    // mean-aggregate features -> agg0 (tf32-rounded)
    agg128_kernel<<<ablocks, 256>>>(features, agg0, n_nodes);
    // h = relu(X@Ws0 + agg0@Wn0 + b0)
    gemm_core<256, 0><<<gblocks, 256, smem_core>>>(
        features, agg0, WT0, b0, h, nullptr, n_nodes);
    // [t | pout] = h @ [Wn1 | Ws1] (+b1 on pout half)
    gemm_core<128, 1><<<gblocks, 256, smem_core>>>(
        h, nullptr, WT1, b1, t, pout, n_nodes);
    // out = pout + mean(t[nbrs])
    agg64_final<<<ablocks, 256>>>(t, pout, (float*)d_out, n_nodes);
}

// round 15
// speedup vs baseline: 1.0376x; 1.0376x over previous
#include <cuda_runtime.h>
#include <mma.h>
#include <cstdint>

using namespace nvcuda;

#define MAX_NODES 100000
#define BUCKET 96

// ---------------------------------------------------------------------------
// Scratch (__device__ globals; no allocation allowed)
// ---------------------------------------------------------------------------
__device__ float g_agg0[(size_t)MAX_NODES * 128];
__device__ float g_h[(size_t)MAX_NODES * 128];
__device__ float g_t[(size_t)MAX_NODES * 64];
__device__ float g_pout[(size_t)MAX_NODES * 64];
__device__ float g_WT0[128 * 256];   // [n][k], tf32-rounded: k<128 Wself0^T, k>=128 Wneigh0^T
__device__ float g_WT1[128 * 128];   // tf32-rounded: rows 0-63 Wneigh1^T, rows 64-127 Wself1^T
__device__ int g_cnt[MAX_NODES];
__device__ int g_bucket[(size_t)MAX_NODES * BUCKET];

// ---------------------------------------------------------------------------
// helpers
// ---------------------------------------------------------------------------
__device__ __forceinline__ void cp16(void* smem_dst, const void* gsrc) {
    uint32_t d = (uint32_t)__cvta_generic_to_shared(smem_dst);
    asm volatile("cp.async.ca.shared.global [%0], [%1], 16;" :: "r"(d), "l"(gsrc));
}
__device__ __forceinline__ void cp_commit() {
    asm volatile("cp.async.commit_group;");
}
__device__ __forceinline__ float to_tf32(float x) {
    float r;
    asm("cvt.rna.tf32.f32 %0, %1;" : "=f"(r) : "f"(x));
    return r;
}

// ---------------------------------------------------------------------------
// Bucketed CSR: vectorized — 4 edges per thread via int4 loads
// ---------------------------------------------------------------------------
__global__ void fill_bucket(const int* __restrict__ src, const int* __restrict__ dst,
                            int n_edges) {
    int e4 = blockIdx.x * blockDim.x + threadIdx.x;
    int base = e4 * 4;
    if (base + 3 < n_edges) {
        int4 s = *reinterpret_cast<const int4*>(src + base);
        int4 d = *reinterpret_cast<const int4*>(dst + base);
        int p0 = atomicAdd(&g_cnt[d.x], 1);
        int p1 = atomicAdd(&g_cnt[d.y], 1);
        int p2 = atomicAdd(&g_cnt[d.z], 1);
        int p3 = atomicAdd(&g_cnt[d.w], 1);
        if (p0 < BUCKET) g_bucket[(size_t)d.x * BUCKET + p0] = s.x;
        if (p1 < BUCKET) g_bucket[(size_t)d.y * BUCKET + p1] = s.y;
        if (p2 < BUCKET) g_bucket[(size_t)d.z * BUCKET + p2] = s.z;
        if (p3 < BUCKET) g_bucket[(size_t)d.w * BUCKET + p3] = s.w;
    } else {
        for (int e = base; e < n_edges; e++) {
            int d = dst[e];
            int pos = atomicAdd(&g_cnt[d], 1);
            if (pos < BUCKET) g_bucket[(size_t)d * BUCKET + pos] = src[e];
        }
    }
}

// ---------------------------------------------------------------------------
// Bucket mean-aggregation (width 128) -> agg0 (tf32-rounded). 4-deep MLP.
// ---------------------------------------------------------------------------
__global__ void agg128_kernel(const float* __restrict__ x, float* __restrict__ out,
                              int n_nodes) {
    int node = (blockIdx.x * blockDim.x + threadIdx.x) >> 5;
    if (node >= n_nodes) return;
    const int lane = threadIdx.x & 31;
    const int deg = g_cnt[node];
    const int cnt = min(deg, BUCKET);
    const int* __restrict__ b = g_bucket + (size_t)node * BUCKET;
    const float inv = 1.0f / (float)max(deg, 1);

    float4 a0 = make_float4(0.f, 0.f, 0.f, 0.f);
    float4 a1 = make_float4(0.f, 0.f, 0.f, 0.f);
    float4 a2 = make_float4(0.f, 0.f, 0.f, 0.f);
    float4 a3 = make_float4(0.f, 0.f, 0.f, 0.f);
    int e = 0;
    for (; e + 3 < cnt; e += 4) {
        int s0 = __ldg(b + e), s1 = __ldg(b + e + 1);
        int s2 = __ldg(b + e + 2), s3 = __ldg(b + e + 3);
        float4 v0 = __ldg((const float4*)(x + (size_t)s0 * 128 + lane * 4));
        float4 v1 = __ldg((const float4*)(x + (size_t)s1 * 128 + lane * 4));
        float4 v2 = __ldg((const float4*)(x + (size_t)s2 * 128 + lane * 4));
        float4 v3 = __ldg((const float4*)(x + (size_t)s3 * 128 + lane * 4));
        a0.x += v0.x; a0.y += v0.y; a0.z += v0.z; a0.w += v0.w;
        a1.x += v1.x; a1.y += v1.y; a1.z += v1.z; a1.w += v1.w;
        a2.x += v2.x; a2.y += v2.y; a2.z += v2.z; a2.w += v2.w;
        a3.x += v3.x; a3.y += v3.y; a3.z += v3.z; a3.w += v3.w;
    }
    for (; e < cnt; e++) {
        int s0 = __ldg(b + e);
        float4 v0 = __ldg((const float4*)(x + (size_t)s0 * 128 + lane * 4));
        a0.x += v0.x; a0.y += v0.y; a0.z += v0.z; a0.w += v0.w;
    }
    float4 r;
    r.x = to_tf32((a0.x + a1.x + a2.x + a3.x) * inv);
    r.y = to_tf32((a0.y + a1.y + a2.y + a3.y) * inv);
    r.z = to_tf32((a0.z + a1.z + a2.z + a3.z) * inv);
    r.w = to_tf32((a0.w + a1.w + a2.w + a3.w) * inv);
    *reinterpret_cast<float4*>(out + (size_t)node * 128 + lane * 4) = r;
}

// ---------------------------------------------------------------------------
// Final fused aggregation (width 64): out = pout + mean(t[nbrs]). 4-deep MLP.
// ---------------------------------------------------------------------------
__global__ void agg64_final(const float* __restrict__ t, const float* __restrict__ pout,
                            float* __restrict__ out, int n_nodes) {
    int node = (blockIdx.x * blockDim.x + threadIdx.x) >> 5;
    if (node >= n_nodes) return;
    const int lane = threadIdx.x & 31;
    const int deg = g_cnt[node];
    const int cnt = min(deg, BUCKET);
    const int* __restrict__ b = g_bucket + (size_t)node * BUCKET;
    const float inv = 1.0f / (float)max(deg, 1);

    float2 a0 = make_float2(0.f, 0.f);
    float2 a1 = make_float2(0.f, 0.f);
    float2 a2 = make_float2(0.f, 0.f);
    float2 a3 = make_float2(0.f, 0.f);
    int e = 0;
    for (; e + 3 < cnt; e += 4) {
        int s0 = __ldg(b + e), s1 = __ldg(b + e + 1);
        int s2 = __ldg(b + e + 2), s3 = __ldg(b + e + 3);
        float2 v0 = __ldg((const float2*)(t + (size_t)s0 * 64 + lane * 2));
        float2 v1 = __ldg((const float2*)(t + (size_t)s1 * 64 + lane * 2));
        float2 v2 = __ldg((const float2*)(t + (size_t)s2 * 64 + lane * 2));
        float2 v3 = __ldg((const float2*)(t + (size_t)s3 * 64 + lane * 2));
        a0.x += v0.x; a0.y += v0.y;
        a1.x += v1.x; a1.y += v1.y;
        a2.x += v2.x; a2.y += v2.y;
        a3.x += v3.x; a3.y += v3.y;
    }
    for (; e < cnt; e++) {
        int s0 = __ldg(b + e);
        float2 v0 = __ldg((const float2*)(t + (size_t)s0 * 64 + lane * 2));
        a0.x += v0.x; a0.y += v0.y;
    }
    float2 p = __ldg((const float2*)(pout + (size_t)node * 64 + lane * 2));
    float2 r;
    r.x = p.x + (a0.x + a1.x + a2.x + a3.x) * inv;
    r.y = p.y + (a0.y + a1.y + a2.y + a3.y) * inv;
    *reinterpret_cast<float2*>(out + (size_t)node * 64 + lane * 2) = r;
}

// ---------------------------------------------------------------------------
// Fused weight transpose, tf32-rounded at source
// ---------------------------------------------------------------------------
__global__ void transpose_all(const float* __restrict__ Wself0,
                              const float* __restrict__ Wneigh0,
                              const float* __restrict__ Wneigh1,
                              const float* __restrict__ Wself1) {
    int i = blockIdx.x * blockDim.x + threadIdx.x;
    if (i < 16384) {
        int k = i >> 7, n = i & 127;
        g_WT0[n * 256 + k] = to_tf32(Wself0[i]);
        g_WT0[n * 256 + 128 + k] = to_tf32(Wneigh0[i]);
    } else {
        i -= 16384;
        if (i < 8192) {
            int k = i >> 6, n = i & 63;
            g_WT1[n * 128 + k] = to_tf32(Wneigh1[i]);
            g_WT1[(64 + n) * 128 + k] = to_tf32(Wself1[i]);
        }
    }
}

// ---------------------------------------------------------------------------
// Shared GEMM core: 256 threads, 8 warps (MW=2 x NW=4), per-warp FM=4 x FN=2.
// BM=128, BN=128. 2 CTAs/SM (<=128 regs, 73.7KB smem).
// MODE 0: h = relu(X@WT0 + Agg@WT0[:,128:] + b)  KTOTAL=256, two A sources
// MODE 1: [t | pout] = X@WT1 (+bias on cols>=64)  KTOTAL=128
// ---------------------------------------------------------------------------
template <int KTOTAL, int MODE>
__global__ void __launch_bounds__(256, 2) gemm_core(
    const float* __restrict__ X, const float* __restrict__ Agg,
    const float* __restrict__ WT, const float* __restrict__ bias,
    float* __restrict__ out0, float* __restrict__ out1, int n_nodes)
{
    constexpr int BM = 128, BN = 128, NCHUNK = KTOTAL / 32;
    constexpr int MW = 2, RM = 64, CN = 32;
    constexpr int FM = 4, FN = 2;
    constexpr int LDS = 36;

    extern __shared__ float smem[];
    float* Xs = smem;                    // 2*128*36 = 9216
    float* Ws = smem + 9216;             // 2*128*36 = 9216  -> 73728 B total
    float* Sbuf = Xs;                    // epilogue staging aliases Xs (dead)

    const int tid = threadIdx.x;
    const int wid = tid >> 5;
    const int lane = tid & 31;
    const int wr = wid % MW;
    const int wc = wid / MW;
    const int block_m = blockIdx.x * BM;

    wmma::fragment<wmma::accumulator, 16, 16, 8, float> acc[FM][FN];
#pragma unroll
    for (int i = 0; i < FM; i++)
#pragma unroll
        for (int j = 0; j < FN; j++) wmma::fill_fragment(acc[i][j], 0.0f);

    auto issue_chunk = [&](int c) {
        const float* __restrict__ srcX = (MODE == 0 && c >= 4) ? Agg : X;
        const int kcol = (MODE == 0) ? (c & 3) * 32 : c * 32;
        float* xbuf = Xs + (c & 1) * BM * LDS;
#pragma unroll
        for (int i = tid; i < BM * 8; i += 256) {
            int m = i >> 3, kq = i & 7;
            int node = min(block_m + m, n_nodes - 1);
            cp16(&xbuf[m * LDS + kq * 4], srcX + (size_t)node * 128 + kcol + kq * 4);
        }
        float* wbuf = Ws + (c & 1) * BN * LDS;
#pragma unroll
        for (int i = tid; i < BN * 8; i += 256) {
            int n = i >> 3, kq = i & 7;
            cp16(&wbuf[n * LDS + kq * 4], WT + (size_t)n * KTOTAL + c * 32 + kq * 4);
        }
        cp_commit();
    };

    issue_chunk(0);

    for (int c = 0; c < NCHUNK; ++c) {
        if (c + 1 < NCHUNK) {
            issue_chunk(c + 1);
            asm volatile("cp.async.wait_group 1;");
        } else {
            asm volatile("cp.async.wait_group 0;");
        }
        __syncthreads();

        const float* xbuf = Xs + (c & 1) * BM * LDS;
        const float* wbuf = Ws + (c & 1) * BN * LDS;

#pragma unroll
        for (int k0 = 0; k0 < 32; k0 += 8) {
            wmma::fragment<wmma::matrix_a, 16, 16, 8, wmma::precision::tf32, wmma::row_major> af[FM];
            wmma::fragment<wmma::matrix_b, 16, 16, 8, wmma::precision::tf32, wmma::col_major> bf[FN];
#pragma unroll
            for (int i = 0; i < FM; i++)
                wmma::load_matrix_sync(af[i], &xbuf[(wr * RM + i * 16) * LDS + k0], LDS);
#pragma unroll
            for (int j = 0; j < FN; j++)
                wmma::load_matrix_sync(bf[j], &wbuf[(wc * CN + j * 16) * LDS + k0], LDS);
#pragma unroll
            for (int i = 0; i < FM; i++)
#pragma unroll
                for (int j = 0; j < FN; j++)
                    wmma::mma_sync(acc[i][j], af[i], bf[j], acc[i][j]);
        }
        __syncthreads();
    }

    // Epilogue
    float* buf = &Sbuf[wid * 256];
#pragma unroll
    for (int i = 0; i < FM; i++) {
#pragma unroll
        for (int j = 0; j < FN; j++) {
            wmma::store_matrix_sync(buf, acc[i][j], 16, wmma::mem_row_major);
            __syncwarp();
            const int r = lane >> 1;
            const int c0 = (lane & 1) * 8;
            const int node = block_m + wr * RM + i * 16 + r;
            const int gcol = wc * CN + j * 16 + c0;
            if (node < n_nodes) {
#pragma unroll
                for (int q = 0; q < 8; q += 4) {
                    float4 v = *reinterpret_cast<const float4*>(&buf[r * 16 + c0 + q]);
                    int n = gcol + q;
                    if (MODE == 0) {
                        float4 bb = *reinterpret_cast<const float4*>(bias + n);
                        v.x = to_tf32(fmaxf(v.x + bb.x, 0.f));
                        v.y = to_tf32(fmaxf(v.y + bb.y, 0.f));
                        v.z = to_tf32(fmaxf(v.z + bb.z, 0.f));
                        v.w = to_tf32(fmaxf(v.w + bb.w, 0.f));
                        *reinterpret_cast<float4*>(out0 + (size_t)node * 128 + n) = v;
                    } else {
                        if (n < 64) {
                            *reinterpret_cast<float4*>(out0 + (size_t)node * 64 + n) = v;
                        } else {
                            int n2 = n - 64;
                            float4 bb = *reinterpret_cast<const float4*>(bias + n2);
                            v.x += bb.x; v.y += bb.y; v.z += bb.z; v.w += bb.w;
                            *reinterpret_cast<float4*>(out1 + (size_t)node * 64 + n2) = v;
                        }
                    }
                }
            }
            __syncwarp();
        }
    }
}

// ---------------------------------------------------------------------------
// Launch (single stream)
// ---------------------------------------------------------------------------
extern "C" void kernel_launch(void* const* d_in, const int* in_sizes, int n_in,
                              void* d_out, int out_size) {
    const float* features = (const float*)d_in[0];
    const int*   src      = (const int*)d_in[1];
    const int*   dst      = (const int*)d_in[2];
    const float* Wself0   = (const float*)d_in[3];
    const float* Wneigh0  = (const float*)d_in[4];
    const float* b0       = (const float*)d_in[5];
    const float* Wself1   = (const float*)d_in[6];
    const float* Wneigh1  = (const float*)d_in[7];
    const float* b1       = (const float*)d_in[8];

    const int n_nodes = in_sizes[0] / 128;
    const int n_edges = in_sizes[1];

    float *agg0, *h, *t, *pout, *WT0, *WT1;
    int* cnt;
    cudaGetSymbolAddress((void**)&agg0, g_agg0);
    cudaGetSymbolAddress((void**)&h, g_h);
    cudaGetSymbolAddress((void**)&t, g_t);
    cudaGetSymbolAddress((void**)&pout, g_pout);
    cudaGetSymbolAddress((void**)&WT0, g_WT0);
    cudaGetSymbolAddress((void**)&WT1, g_WT1);
    cudaGetSymbolAddress((void**)&cnt, g_cnt);

    const int smem_core = 18432 * 4;  // 73728 B -> 2 CTAs/SM
    static bool attr_set = false;
    if (!attr_set) {
        cudaFuncSetAttribute((const void*)gemm_core<256, 0>,
                             cudaFuncAttributeMaxDynamicSharedMemorySize, smem_core);
        cudaFuncSetAttribute((const void*)gemm_core<128, 1>,
                             cudaFuncAttributeMaxDynamicSharedMemorySize, smem_core);
        attr_set = true;
    }

    cudaMemsetAsync(cnt, 0, sizeof(int) * (size_t)n_nodes, 0);

    transpose_all<<<(24576 + 255) / 256, 256>>>(Wself0, Wneigh0, Wneigh1, Wself1);
    {
        int n4 = (n_edges + 3) / 4;
        fill_bucket<<<(n4 + 255) / 256, 256>>>(src, dst, n_edges);
    }

    const int gblocks = (n_nodes + 127) / 128;
    const int ablocks = (int)(((long long)n_nodes * 32 + 255) / 256);

    // mean-aggregate features -> agg0 (tf32-rounded)
    agg128_kernel<<<ablocks, 256>>>(features, agg0, n_nodes);
    // h = relu(X@Ws0 + agg0@Wn0 + b0)
    gemm_core<256, 0><<<gblocks, 256, smem_core>>>(
        features, agg0, WT0, b0, h, nullptr, n_nodes);
    // [t | pout] = h @ [Wn1 | Ws1] (+b1 on pout half)
    gemm_core<128, 1><<<gblocks, 256, smem_core>>>(
        h, nullptr, WT1, b1, t, pout, n_nodes);
    // out = pout + mean(t[nbrs])
    agg64_final<<<ablocks, 256>>>(t, pout, (float*)d_out, n_nodes);
}

// round 16
// speedup vs baseline: 1.0790x; 1.0399x over previous
#include <cuda_runtime.h>
#include <cuda_fp16.h>
#include <mma.h>
#include <cstdint>

using namespace nvcuda;

#define MAX_NODES 100000
#define BUCKET 96

// ---------------------------------------------------------------------------
// Scratch (__device__ globals; no allocation allowed)
// ---------------------------------------------------------------------------
__device__ float g_agg0[(size_t)MAX_NODES * 128];
__device__ float g_h[(size_t)MAX_NODES * 128];
__device__ __half g_feat16[(size_t)MAX_NODES * 128];   // fp16 copy of features (gather path)
__device__ __half g_t16[(size_t)MAX_NODES * 64];       // t = h@Wn1, fp16
__device__ float g_pout[(size_t)MAX_NODES * 64];
__device__ float g_WT0[128 * 256];   // [n][k], tf32-rounded: k<128 Wself0^T, k>=128 Wneigh0^T
__device__ float g_WT1[128 * 128];   // tf32-rounded: rows 0-63 Wneigh1^T, rows 64-127 Wself1^T
__device__ int g_cnt[MAX_NODES];
__device__ int g_bucket[(size_t)MAX_NODES * BUCKET];

// ---------------------------------------------------------------------------
// helpers
// ---------------------------------------------------------------------------
__device__ __forceinline__ void cp16(void* smem_dst, const void* gsrc) {
    uint32_t d = (uint32_t)__cvta_generic_to_shared(smem_dst);
    asm volatile("cp.async.ca.shared.global [%0], [%1], 16;" :: "r"(d), "l"(gsrc));
}
__device__ __forceinline__ void cp_commit() {
    asm volatile("cp.async.commit_group;");
}
__device__ __forceinline__ float to_tf32(float x) {
    float r;
    asm("cvt.rna.tf32.f32 %0, %1;" : "=f"(r) : "f"(x));
    return r;
}

// ---------------------------------------------------------------------------
// features -> fp16 copy (gather path only; GEMMs keep fp32 source)
// ---------------------------------------------------------------------------
__global__ void convert_feat(const float* __restrict__ x, __half* __restrict__ xh,
                             int n_elems8) {
    int i = blockIdx.x * blockDim.x + threadIdx.x;
    if (i < n_elems8) {
        const float4 v0 = __ldg((const float4*)(x + (size_t)i * 8));
        const float4 v1 = __ldg((const float4*)(x + (size_t)i * 8 + 4));
        __half2 h0 = __floats2half2_rn(v0.x, v0.y);
        __half2 h1 = __floats2half2_rn(v0.z, v0.w);
        __half2 h2 = __floats2half2_rn(v1.x, v1.y);
        __half2 h3 = __floats2half2_rn(v1.z, v1.w);
        uint4 u;
        u.x = *reinterpret_cast<uint32_t*>(&h0);
        u.y = *reinterpret_cast<uint32_t*>(&h1);
        u.z = *reinterpret_cast<uint32_t*>(&h2);
        u.w = *reinterpret_cast<uint32_t*>(&h3);
        *reinterpret_cast<uint4*>(xh + (size_t)i * 8) = u;
    }
}

// ---------------------------------------------------------------------------
// Bucketed CSR: vectorized — 4 edges per thread via int4 loads
// ---------------------------------------------------------------------------
__global__ void fill_bucket(const int* __restrict__ src, const int* __restrict__ dst,
                            int n_edges) {
    int e4 = blockIdx.x * blockDim.x + threadIdx.x;
    int base = e4 * 4;
    if (base + 3 < n_edges) {
        int4 s = *reinterpret_cast<const int4*>(src + base);
        int4 d = *reinterpret_cast<const int4*>(dst + base);
        int p0 = atomicAdd(&g_cnt[d.x], 1);
        int p1 = atomicAdd(&g_cnt[d.y], 1);
        int p2 = atomicAdd(&g_cnt[d.z], 1);
        int p3 = atomicAdd(&g_cnt[d.w], 1);
        if (p0 < BUCKET) g_bucket[(size_t)d.x * BUCKET + p0] = s.x;
        if (p1 < BUCKET) g_bucket[(size_t)d.y * BUCKET + p1] = s.y;
        if (p2 < BUCKET) g_bucket[(size_t)d.z * BUCKET + p2] = s.z;
        if (p3 < BUCKET) g_bucket[(size_t)d.w * BUCKET + p3] = s.w;
    } else {
        for (int e = base; e < n_edges; e++) {
            int d = dst[e];
            int pos = atomicAdd(&g_cnt[d], 1);
            if (pos < BUCKET) g_bucket[(size_t)d * BUCKET + pos] = src[e];
        }
    }
}

// ---------------------------------------------------------------------------
// fp16 mean-aggregation (width 128) -> agg0 fp32 (tf32-rounded).
// One warp per node; lane owns cols [4l,4l+4); 8B gather per lane per edge.
// ---------------------------------------------------------------------------
__global__ void agg128_kernel(const __half* __restrict__ xh, float* __restrict__ out,
                              int n_nodes) {
    int node = (blockIdx.x * blockDim.x + threadIdx.x) >> 5;
    if (node >= n_nodes) return;
    const int lane = threadIdx.x & 31;
    const int deg = g_cnt[node];
    const int cnt = min(deg, BUCKET);
    const int* __restrict__ b = g_bucket + (size_t)node * BUCKET;
    const float inv = 1.0f / (float)max(deg, 1);

    float4 a0 = make_float4(0.f, 0.f, 0.f, 0.f);
    float4 a1 = make_float4(0.f, 0.f, 0.f, 0.f);
    float4 a2 = make_float4(0.f, 0.f, 0.f, 0.f);
    float4 a3 = make_float4(0.f, 0.f, 0.f, 0.f);
    int e = 0;
    for (; e + 3 < cnt; e += 4) {
        int s0 = __ldg(b + e), s1 = __ldg(b + e + 1);
        int s2 = __ldg(b + e + 2), s3 = __ldg(b + e + 3);
        uint2 u0 = __ldg((const uint2*)(xh + (size_t)s0 * 128 + lane * 4));
        uint2 u1 = __ldg((const uint2*)(xh + (size_t)s1 * 128 + lane * 4));
        uint2 u2 = __ldg((const uint2*)(xh + (size_t)s2 * 128 + lane * 4));
        uint2 u3 = __ldg((const uint2*)(xh + (size_t)s3 * 128 + lane * 4));
        float2 f;
        f = __half22float2(*reinterpret_cast<__half2*>(&u0.x)); a0.x += f.x; a0.y += f.y;
        f = __half22float2(*reinterpret_cast<__half2*>(&u0.y)); a0.z += f.x; a0.w += f.y;
        f = __half22float2(*reinterpret_cast<__half2*>(&u1.x)); a1.x += f.x; a1.y += f.y;
        f = __half22float2(*reinterpret_cast<__half2*>(&u1.y)); a1.z += f.x; a1.w += f.y;
        f = __half22float2(*reinterpret_cast<__half2*>(&u2.x)); a2.x += f.x; a2.y += f.y;
        f = __half22float2(*reinterpret_cast<__half2*>(&u2.y)); a2.z += f.x; a2.w += f.y;
        f = __half22float2(*reinterpret_cast<__half2*>(&u3.x)); a3.x += f.x; a3.y += f.y;
        f = __half22float2(*reinterpret_cast<__half2*>(&u3.y)); a3.z += f.x; a3.w += f.y;
    }
    for (; e < cnt; e++) {
        int s0 = __ldg(b + e);
        uint2 u0 = __ldg((const uint2*)(xh + (size_t)s0 * 128 + lane * 4));
        float2 f;
        f = __half22float2(*reinterpret_cast<__half2*>(&u0.x)); a0.x += f.x; a0.y += f.y;
        f = __half22float2(*reinterpret_cast<__half2*>(&u0.y)); a0.z += f.x; a0.w += f.y;
    }
    float4 r;
    r.x = to_tf32((a0.x + a1.x + a2.x + a3.x) * inv);
    r.y = to_tf32((a0.y + a1.y + a2.y + a3.y) * inv);
    r.z = to_tf32((a0.z + a1.z + a2.z + a3.z) * inv);
    r.w = to_tf32((a0.w + a1.w + a2.w + a3.w) * inv);
    *reinterpret_cast<float4*>(out + (size_t)node * 128 + lane * 4) = r;
}

// ---------------------------------------------------------------------------
// Final fused aggregation: out = pout + mean(t16[nbrs]); lane owns cols [2l,2l+2)
// ---------------------------------------------------------------------------
__global__ void agg64_final(const __half* __restrict__ th, const float* __restrict__ pout,
                            float* __restrict__ out, int n_nodes) {
    int node = (blockIdx.x * blockDim.x + threadIdx.x) >> 5;
    if (node >= n_nodes) return;
    const int lane = threadIdx.x & 31;
    const int deg = g_cnt[node];
    const int cnt = min(deg, BUCKET);
    const int* __restrict__ b = g_bucket + (size_t)node * BUCKET;
    const float inv = 1.0f / (float)max(deg, 1);

    float2 a0 = make_float2(0.f, 0.f);
    float2 a1 = make_float2(0.f, 0.f);
    float2 a2 = make_float2(0.f, 0.f);
    float2 a3 = make_float2(0.f, 0.f);
    int e = 0;
    for (; e + 3 < cnt; e += 4) {
        int s0 = __ldg(b + e), s1 = __ldg(b + e + 1);
        int s2 = __ldg(b + e + 2), s3 = __ldg(b + e + 3);
        uint32_t u0 = __ldg((const uint32_t*)(th + (size_t)s0 * 64 + lane * 2));
        uint32_t u1 = __ldg((const uint32_t*)(th + (size_t)s1 * 64 + lane * 2));
        uint32_t u2 = __ldg((const uint32_t*)(th + (size_t)s2 * 64 + lane * 2));
        uint32_t u3 = __ldg((const uint32_t*)(th + (size_t)s3 * 64 + lane * 2));
        float2 f;
        f = __half22float2(*reinterpret_cast<__half2*>(&u0)); a0.x += f.x; a0.y += f.y;
        f = __half22float2(*reinterpret_cast<__half2*>(&u1)); a1.x += f.x; a1.y += f.y;
        f = __half22float2(*reinterpret_cast<__half2*>(&u2)); a2.x += f.x; a2.y += f.y;
        f = __half22float2(*reinterpret_cast<__half2*>(&u3)); a3.x += f.x; a3.y += f.y;
    }
    for (; e < cnt; e++) {
        int s0 = __ldg(b + e);
        uint32_t u0 = __ldg((const uint32_t*)(th + (size_t)s0 * 64 + lane * 2));
        float2 f = __half22float2(*reinterpret_cast<__half2*>(&u0));
        a0.x += f.x; a0.y += f.y;
    }
    float2 p = __ldg((const float2*)(pout + (size_t)node * 64 + lane * 2));
    float2 r;
    r.x = p.x + (a0.x + a1.x + a2.x + a3.x) * inv;
    r.y = p.y + (a0.y + a1.y + a2.y + a3.y) * inv;
    *reinterpret_cast<float2*>(out + (size_t)node * 64 + lane * 2) = r;
}

// ---------------------------------------------------------------------------
// Fused weight transpose, tf32-rounded at source
// ---------------------------------------------------------------------------
__global__ void transpose_all(const float* __restrict__ Wself0,
                              const float* __restrict__ Wneigh0,
                              const float* __restrict__ Wneigh1,
                              const float* __restrict__ Wself1) {
    int i = blockIdx.x * blockDim.x + threadIdx.x;
    if (i < 16384) {
        int k = i >> 7, n = i & 127;
        g_WT0[n * 256 + k] = to_tf32(Wself0[i]);
        g_WT0[n * 256 + 128 + k] = to_tf32(Wneigh0[i]);
    } else {
        i -= 16384;
        if (i < 8192) {
            int k = i >> 6, n = i & 63;
            g_WT1[n * 128 + k] = to_tf32(Wneigh1[i]);
            g_WT1[(64 + n) * 128 + k] = to_tf32(Wself1[i]);
        }
    }
}

// ---------------------------------------------------------------------------
// Shared GEMM core: 256 threads, 8 warps (MW=2 x NW=4), per-warp FM=4 x FN=2.
// BM=128, BN=128. 2 CTAs/SM (<=128 regs, 73.7KB smem).
// MODE 0: h = relu(X@WT0 + Agg@WT0[:,128:] + b)  KTOTAL=256, two A sources
// MODE 1: [t16 | pout] = X@WT1 (+bias on cols>=64); t half, pout fp32
// ---------------------------------------------------------------------------
template <int KTOTAL, int MODE>
__global__ void __launch_bounds__(256, 2) gemm_core(
    const float* __restrict__ X, const float* __restrict__ Agg,
    const float* __restrict__ WT, const float* __restrict__ bias,
    float* __restrict__ out0, float* __restrict__ out1, int n_nodes)
{
    constexpr int BM = 128, BN = 128, NCHUNK = KTOTAL / 32;
    constexpr int MW = 2, RM = 64, CN = 32;
    constexpr int FM = 4, FN = 2;
    constexpr int LDS = 36;

    extern __shared__ float smem[];
    float* Xs = smem;                    // 2*128*36 = 9216
    float* Ws = smem + 9216;             // 2*128*36 = 9216  -> 73728 B total
    float* Sbuf = Xs;                    // epilogue staging aliases Xs (dead)

    const int tid = threadIdx.x;
    const int wid = tid >> 5;
    const int lane = tid & 31;
    const int wr = wid % MW;
    const int wc = wid / MW;
    const int block_m = blockIdx.x * BM;

    wmma::fragment<wmma::accumulator, 16, 16, 8, float> acc[FM][FN];
#pragma unroll
    for (int i = 0; i < FM; i++)
#pragma unroll
        for (int j = 0; j < FN; j++) wmma::fill_fragment(acc[i][j], 0.0f);

    auto issue_chunk = [&](int c) {
        const float* __restrict__ srcX = (MODE == 0 && c >= 4) ? Agg : X;
        const int kcol = (MODE == 0) ? (c & 3) * 32 : c * 32;
        float* xbuf = Xs + (c & 1) * BM * LDS;
#pragma unroll
        for (int i = tid; i < BM * 8; i += 256) {
            int m = i >> 3, kq = i & 7;
            int node = min(block_m + m, n_nodes - 1);
            cp16(&xbuf[m * LDS + kq * 4], srcX + (size_t)node * 128 + kcol + kq * 4);
        }
        float* wbuf = Ws + (c & 1) * BN * LDS;
#pragma unroll
        for (int i = tid; i < BN * 8; i += 256) {
            int n = i >> 3, kq = i & 7;
            cp16(&wbuf[n * LDS + kq * 4], WT + (size_t)n * KTOTAL + c * 32 + kq * 4);
        }
        cp_commit();
    };

    issue_chunk(0);

    for (int c = 0; c < NCHUNK; ++c) {
        if (c + 1 < NCHUNK) {
            issue_chunk(c + 1);
            asm volatile("cp.async.wait_group 1;");
        } else {
            asm volatile("cp.async.wait_group 0;");
        }
        __syncthreads();

        const float* xbuf = Xs + (c & 1) * BM * LDS;
        const float* wbuf = Ws + (c & 1) * BN * LDS;

#pragma unroll
        for (int k0 = 0; k0 < 32; k0 += 8) {
            wmma::fragment<wmma::matrix_a, 16, 16, 8, wmma::precision::tf32, wmma::row_major> af[FM];
            wmma::fragment<wmma::matrix_b, 16, 16, 8, wmma::precision::tf32, wmma::col_major> bf[FN];
#pragma unroll
            for (int i = 0; i < FM; i++)
                wmma::load_matrix_sync(af[i], &xbuf[(wr * RM + i * 16) * LDS + k0], LDS);
#pragma unroll
            for (int j = 0; j < FN; j++)
                wmma::load_matrix_sync(bf[j], &wbuf[(wc * CN + j * 16) * LDS + k0], LDS);
#pragma unroll
            for (int i = 0; i < FM; i++)
#pragma unroll
                for (int j = 0; j < FN; j++)
                    wmma::mma_sync(acc[i][j], af[i], bf[j], acc[i][j]);
        }
        __syncthreads();
    }

    // Epilogue
    float* buf = &Sbuf[wid * 256];
#pragma unroll
    for (int i = 0; i < FM; i++) {
#pragma unroll
        for (int j = 0; j < FN; j++) {
            wmma::store_matrix_sync(buf, acc[i][j], 16, wmma::mem_row_major);
            __syncwarp();
            const int r = lane >> 1;
            const int c0 = (lane & 1) * 8;
            const int node = block_m + wr * RM + i * 16 + r;
            const int gcol = wc * CN + j * 16 + c0;
            if (node < n_nodes) {
#pragma unroll
                for (int q = 0; q < 8; q += 4) {
                    float4 v = *reinterpret_cast<const float4*>(&buf[r * 16 + c0 + q]);
                    int n = gcol + q;
                    if (MODE == 0) {
                        float4 bb = *reinterpret_cast<const float4*>(bias + n);
                        v.x = to_tf32(fmaxf(v.x + bb.x, 0.f));
                        v.y = to_tf32(fmaxf(v.y + bb.y, 0.f));
                        v.z = to_tf32(fmaxf(v.z + bb.z, 0.f));
                        v.w = to_tf32(fmaxf(v.w + bb.w, 0.f));
                        *reinterpret_cast<float4*>(out0 + (size_t)node * 128 + n) = v;
                    } else {
                        if (n < 64) {
                            // t stored as fp16
                            __half2 h01 = __floats2half2_rn(v.x, v.y);
                            __half2 h23 = __floats2half2_rn(v.z, v.w);
                            uint2 u;
                            u.x = *reinterpret_cast<uint32_t*>(&h01);
                            u.y = *reinterpret_cast<uint32_t*>(&h23);
                            __half* t16 = reinterpret_cast<__half*>(out0);
                            *reinterpret_cast<uint2*>(t16 + (size_t)node * 64 + n) = u;
                        } else {
                            int n2 = n - 64;
                            float4 bb = *reinterpret_cast<const float4*>(bias + n2);
                            v.x += bb.x; v.y += bb.y; v.z += bb.z; v.w += bb.w;
                            *reinterpret_cast<float4*>(out1 + (size_t)node * 64 + n2) = v;
                        }
                    }
                }
            }
            __syncwarp();
        }
    }
}

// ---------------------------------------------------------------------------
// Launch (single stream)
// ---------------------------------------------------------------------------
extern "C" void kernel_launch(void* const* d_in, const int* in_sizes, int n_in,
                              void* d_out, int out_size) {
    const float* features = (const float*)d_in[0];
    const int*   src      = (const int*)d_in[1];
    const int*   dst      = (const int*)d_in[2];
    const float* Wself0   = (const float*)d_in[3];
    const float* Wneigh0  = (const float*)d_in[4];
    const float* b0       = (const float*)d_in[5];
    const float* Wself1   = (const float*)d_in[6];
    const float* Wneigh1  = (const float*)d_in[7];
    const float* b1       = (const float*)d_in[8];

    const int n_nodes = in_sizes[0] / 128;
    const int n_edges = in_sizes[1];

    float *agg0, *h, *pout, *WT0, *WT1;
    __half *feat16, *t16;
    int* cnt;
    cudaGetSymbolAddress((void**)&agg0, g_agg0);
    cudaGetSymbolAddress((void**)&h, g_h);
    cudaGetSymbolAddress((void**)&feat16, g_feat16);
    cudaGetSymbolAddress((void**)&t16, g_t16);
    cudaGetSymbolAddress((void**)&pout, g_pout);
    cudaGetSymbolAddress((void**)&WT0, g_WT0);
    cudaGetSymbolAddress((void**)&WT1, g_WT1);
    cudaGetSymbolAddress((void**)&cnt, g_cnt);

    const int smem_core = 18432 * 4;  // 73728 B -> 2 CTAs/SM
    static bool attr_set = false;
    if (!attr_set) {
        cudaFuncSetAttribute((const void*)gemm_core<256, 0>,
                             cudaFuncAttributeMaxDynamicSharedMemorySize, smem_core);
        cudaFuncSetAttribute((const void*)gemm_core<128, 1>,
                             cudaFuncAttributeMaxDynamicSharedMemorySize, smem_core);
        attr_set = true;
    }

    cudaMemsetAsync(cnt, 0, sizeof(int) * (size_t)n_nodes, 0);

    transpose_all<<<(24576 + 255) / 256, 256>>>(Wself0, Wneigh0, Wneigh1, Wself1);
    {
        int n8 = (n_nodes * 128) / 8;
        convert_feat<<<(n8 + 255) / 256, 256>>>(features, feat16, n8);
    }
    {
        int n4 = (n_edges + 3) / 4;
        fill_bucket<<<(n4 + 255) / 256, 256>>>(src, dst, n_edges);
    }

    const int gblocks = (n_nodes + 127) / 128;
    const int ablocks = (int)(((long long)n_nodes * 32 + 255) / 256);

    // mean-aggregate fp16 features -> agg0 (fp32, tf32-rounded)
    agg128_kernel<<<ablocks, 256>>>(feat16, agg0, n_nodes);
    // h = relu(X@Ws0 + agg0@Wn0 + b0)
    gemm_core<256, 0><<<gblocks, 256, smem_core>>>(
        features, agg0, WT0, b0, h, nullptr, n_nodes);
    // [t16 | pout] = h @ [Wn1 | Ws1] (+b1 on pout half); t stored fp16
    gemm_core<128, 1><<<gblocks, 256, smem_core>>>(
        h, nullptr, WT1, b1, (float*)t16, pout, n_nodes);
    // out = pout + mean(t16[nbrs])
    agg64_final<<<ablocks, 256>>>(t16, pout, (float*)d_out, n_nodes);
}

// round 17
// speedup vs baseline: 1.6085x; 1.4908x over previous
#include <cuda_runtime.h>
#include <cuda_fp16.h>
#include <mma.h>
#include <cstdint>

using namespace nvcuda;

#define MAX_NODES 100000
#define BUCKET 96

// ---------------------------------------------------------------------------
// Scratch (__device__ globals; no allocation allowed)
// ---------------------------------------------------------------------------
__device__ __half g_feat16[(size_t)MAX_NODES * 128];   // fp16 features (gather + GEMM A)
__device__ __half g_agg0[(size_t)MAX_NODES * 128];     // fp16 mean aggregate
__device__ __half g_h16[(size_t)MAX_NODES * 128];      // fp16 h
__device__ __half g_t16[(size_t)MAX_NODES * 64];       // fp16 t = h@Wn1
__device__ float g_pout[(size_t)MAX_NODES * 64];
__device__ __half g_WT0[128 * 256];   // [n][k] fp16: k<128 Wself0^T, k>=128 Wneigh0^T
__device__ __half g_WT1[128 * 128];   // fp16: rows 0-63 Wneigh1^T, rows 64-127 Wself1^T
__device__ int g_cnt[MAX_NODES];
__device__ int g_bucket[(size_t)MAX_NODES * BUCKET];

// ---------------------------------------------------------------------------
// helpers
// ---------------------------------------------------------------------------
__device__ __forceinline__ void cp16(void* smem_dst, const void* gsrc) {
    uint32_t d = (uint32_t)__cvta_generic_to_shared(smem_dst);
    asm volatile("cp.async.ca.shared.global [%0], [%1], 16;" :: "r"(d), "l"(gsrc));
}
__device__ __forceinline__ void cp_commit() {
    asm volatile("cp.async.commit_group;");
}

// ---------------------------------------------------------------------------
// features -> fp16 copy
// ---------------------------------------------------------------------------
__global__ void convert_feat(const float* __restrict__ x, __half* __restrict__ xh,
                             int n_elems8) {
    int i = blockIdx.x * blockDim.x + threadIdx.x;
    if (i < n_elems8) {
        const float4 v0 = __ldg((const float4*)(x + (size_t)i * 8));
        const float4 v1 = __ldg((const float4*)(x + (size_t)i * 8 + 4));
        __half2 h0 = __floats2half2_rn(v0.x, v0.y);
        __half2 h1 = __floats2half2_rn(v0.z, v0.w);
        __half2 h2 = __floats2half2_rn(v1.x, v1.y);
        __half2 h3 = __floats2half2_rn(v1.z, v1.w);
        uint4 u;
        u.x = *reinterpret_cast<uint32_t*>(&h0);
        u.y = *reinterpret_cast<uint32_t*>(&h1);
        u.z = *reinterpret_cast<uint32_t*>(&h2);
        u.w = *reinterpret_cast<uint32_t*>(&h3);
        *reinterpret_cast<uint4*>(xh + (size_t)i * 8) = u;
    }
}

// ---------------------------------------------------------------------------
// Bucketed CSR: 4 edges per thread via int4 loads
// ---------------------------------------------------------------------------
__global__ void fill_bucket(const int* __restrict__ src, const int* __restrict__ dst,
                            int n_edges) {
    int e4 = blockIdx.x * blockDim.x + threadIdx.x;
    int base = e4 * 4;
    if (base + 3 < n_edges) {
        int4 s = *reinterpret_cast<const int4*>(src + base);
        int4 d = *reinterpret_cast<const int4*>(dst + base);
        int p0 = atomicAdd(&g_cnt[d.x], 1);
        int p1 = atomicAdd(&g_cnt[d.y], 1);
        int p2 = atomicAdd(&g_cnt[d.z], 1);
        int p3 = atomicAdd(&g_cnt[d.w], 1);
        if (p0 < BUCKET) g_bucket[(size_t)d.x * BUCKET + p0] = s.x;
        if (p1 < BUCKET) g_bucket[(size_t)d.y * BUCKET + p1] = s.y;
        if (p2 < BUCKET) g_bucket[(size_t)d.z * BUCKET + p2] = s.z;
        if (p3 < BUCKET) g_bucket[(size_t)d.w * BUCKET + p3] = s.w;
    } else {
        for (int e = base; e < n_edges; e++) {
            int d = dst[e];
            int pos = atomicAdd(&g_cnt[d], 1);
            if (pos < BUCKET) g_bucket[(size_t)d * BUCKET + pos] = src[e];
        }
    }
}

// ---------------------------------------------------------------------------
// fp16 mean-aggregation (width 128) -> agg0 fp16. fp32 accumulation.
// ---------------------------------------------------------------------------
__global__ void agg128_kernel(const __half* __restrict__ xh, __half* __restrict__ out,
                              int n_nodes) {
    int node = (blockIdx.x * blockDim.x + threadIdx.x) >> 5;
    if (node >= n_nodes) return;
    const int lane = threadIdx.x & 31;
    const int deg = g_cnt[node];
    const int cnt = min(deg, BUCKET);
    const int* __restrict__ b = g_bucket + (size_t)node * BUCKET;
    const float inv = 1.0f / (float)max(deg, 1);

    float4 a0 = make_float4(0.f, 0.f, 0.f, 0.f);
    float4 a1 = make_float4(0.f, 0.f, 0.f, 0.f);
    float4 a2 = make_float4(0.f, 0.f, 0.f, 0.f);
    float4 a3 = make_float4(0.f, 0.f, 0.f, 0.f);
    int e = 0;
    for (; e + 3 < cnt; e += 4) {
        int s0 = __ldg(b + e), s1 = __ldg(b + e + 1);
        int s2 = __ldg(b + e + 2), s3 = __ldg(b + e + 3);
        uint2 u0 = __ldg((const uint2*)(xh + (size_t)s0 * 128 + lane * 4));
        uint2 u1 = __ldg((const uint2*)(xh + (size_t)s1 * 128 + lane * 4));
        uint2 u2 = __ldg((const uint2*)(xh + (size_t)s2 * 128 + lane * 4));
        uint2 u3 = __ldg((const uint2*)(xh + (size_t)s3 * 128 + lane * 4));
        float2 f;
        f = __half22float2(*reinterpret_cast<__half2*>(&u0.x)); a0.x += f.x; a0.y += f.y;
        f = __half22float2(*reinterpret_cast<__half2*>(&u0.y)); a0.z += f.x; a0.w += f.y;
        f = __half22float2(*reinterpret_cast<__half2*>(&u1.x)); a1.x += f.x; a1.y += f.y;
        f = __half22float2(*reinterpret_cast<__half2*>(&u1.y)); a1.z += f.x; a1.w += f.y;
        f = __half22float2(*reinterpret_cast<__half2*>(&u2.x)); a2.x += f.x; a2.y += f.y;
        f = __half22float2(*reinterpret_cast<__half2*>(&u2.y)); a2.z += f.x; a2.w += f.y;
        f = __half22float2(*reinterpret_cast<__half2*>(&u3.x)); a3.x += f.x; a3.y += f.y;
        f = __half22float2(*reinterpret_cast<__half2*>(&u3.y)); a3.z += f.x; a3.w += f.y;
    }
    for (; e < cnt; e++) {
        int s0 = __ldg(b + e);
        uint2 u0 = __ldg((const uint2*)(xh + (size_t)s0 * 128 + lane * 4));
        float2 f;
        f = __half22float2(*reinterpret_cast<__half2*>(&u0.x)); a0.x += f.x; a0.y += f.y;
        f = __half22float2(*reinterpret_cast<__half2*>(&u0.y)); a0.z += f.x; a0.w += f.y;
    }
    __half2 r0 = __floats2half2_rn((a0.x + a1.x + a2.x + a3.x) * inv,
                                   (a0.y + a1.y + a2.y + a3.y) * inv);
    __half2 r1 = __floats2half2_rn((a0.z + a1.z + a2.z + a3.z) * inv,
                                   (a0.w + a1.w + a2.w + a3.w) * inv);
    uint2 u;
    u.x = *reinterpret_cast<uint32_t*>(&r0);
    u.y = *reinterpret_cast<uint32_t*>(&r1);
    *reinterpret_cast<uint2*>(out + (size_t)node * 128 + lane * 4) = u;
}

// ---------------------------------------------------------------------------
// Final fused aggregation: out = pout + mean(t16[nbrs])
// ---------------------------------------------------------------------------
__global__ void agg64_final(const __half* __restrict__ th, const float* __restrict__ pout,
                            float* __restrict__ out, int n_nodes) {
    int node = (blockIdx.x * blockDim.x + threadIdx.x) >> 5;
    if (node >= n_nodes) return;
    const int lane = threadIdx.x & 31;
    const int deg = g_cnt[node];
    const int cnt = min(deg, BUCKET);
    const int* __restrict__ b = g_bucket + (size_t)node * BUCKET;
    const float inv = 1.0f / (float)max(deg, 1);

    float2 a0 = make_float2(0.f, 0.f);
    float2 a1 = make_float2(0.f, 0.f);
    float2 a2 = make_float2(0.f, 0.f);
    float2 a3 = make_float2(0.f, 0.f);
    int e = 0;
    for (; e + 3 < cnt; e += 4) {
        int s0 = __ldg(b + e), s1 = __ldg(b + e + 1);
        int s2 = __ldg(b + e + 2), s3 = __ldg(b + e + 3);
        uint32_t u0 = __ldg((const uint32_t*)(th + (size_t)s0 * 64 + lane * 2));
        uint32_t u1 = __ldg((const uint32_t*)(th + (size_t)s1 * 64 + lane * 2));
        uint32_t u2 = __ldg((const uint32_t*)(th + (size_t)s2 * 64 + lane * 2));
        uint32_t u3 = __ldg((const uint32_t*)(th + (size_t)s3 * 64 + lane * 2));
        float2 f;
        f = __half22float2(*reinterpret_cast<__half2*>(&u0)); a0.x += f.x; a0.y += f.y;
        f = __half22float2(*reinterpret_cast<__half2*>(&u1)); a1.x += f.x; a1.y += f.y;
        f = __half22float2(*reinterpret_cast<__half2*>(&u2)); a2.x += f.x; a2.y += f.y;
        f = __half22float2(*reinterpret_cast<__half2*>(&u3)); a3.x += f.x; a3.y += f.y;
    }
    for (; e < cnt; e++) {
        int s0 = __ldg(b + e);
        uint32_t u0 = __ldg((const uint32_t*)(th + (size_t)s0 * 64 + lane * 2));
        float2 f = __half22float2(*reinterpret_cast<__half2*>(&u0));
        a0.x += f.x; a0.y += f.y;
    }
    float2 p = __ldg((const float2*)(pout + (size_t)node * 64 + lane * 2));
    float2 r;
    r.x = p.x + (a0.x + a1.x + a2.x + a3.x) * inv;
    r.y = p.y + (a0.y + a1.y + a2.y + a3.y) * inv;
    *reinterpret_cast<float2*>(out + (size_t)node * 64 + lane * 2) = r;
}

// ---------------------------------------------------------------------------
// Fused weight transpose -> fp16
// ---------------------------------------------------------------------------
__global__ void transpose_all(const float* __restrict__ Wself0,
                              const float* __restrict__ Wneigh0,
                              const float* __restrict__ Wneigh1,
                              const float* __restrict__ Wself1) {
    int i = blockIdx.x * blockDim.x + threadIdx.x;
    if (i < 16384) {
        int k = i >> 7, n = i & 127;
        g_WT0[n * 256 + k] = __float2half(Wself0[i]);
        g_WT0[n * 256 + 128 + k] = __float2half(Wneigh0[i]);
    } else {
        i -= 16384;
        if (i < 8192) {
            int k = i >> 6, n = i & 63;
            g_WT1[n * 128 + k] = __float2half(Wneigh1[i]);
            g_WT1[(64 + n) * 128 + k] = __float2half(Wself1[i]);
        }
    }
}

// ---------------------------------------------------------------------------
// fp16 GEMM core: 256 threads, 8 warps (MW=2 x NW=4), per-warp FM=4 x FN=2.
// m16n16k16 half MMA, fp32 accum. BM=128, BN=128. 2 CTAs/SM, ~40KB smem.
// MODE 0: h16 = relu(X16@WT0 + Agg16@WT0[:,128:] + b)  KTOTAL=256
// MODE 1: [t16 | pout] = X16@WT1 (+bias on cols>=64)    KTOTAL=128
// ---------------------------------------------------------------------------
template <int KTOTAL, int MODE>
__global__ void __launch_bounds__(256, 2) gemm_core(
    const __half* __restrict__ X, const __half* __restrict__ Agg,
    const __half* __restrict__ WT, const float* __restrict__ bias,
    void* __restrict__ out0, float* __restrict__ out1, int n_nodes)
{
    constexpr int BM = 128, BN = 128, NCHUNK = KTOTAL / 32;
    constexpr int MW = 2, RM = 64, CN = 32;
    constexpr int FM = 4, FN = 2;
    constexpr int LDS = 40;  // halves; 80B rows, 16B-aligned

    extern __shared__ char smem[];
    __half* Xs = (__half*)smem;                        // 2*128*40*2 = 20480 B
    __half* Ws = (__half*)(smem + 20480);              // 20480 B -> 40960 total
    float* Sbuf = (float*)smem;                        // epilogue staging (Xs dead)

    const int tid = threadIdx.x;
    const int wid = tid >> 5;
    const int lane = tid & 31;
    const int wr = wid % MW;
    const int wc = wid / MW;
    const int block_m = blockIdx.x * BM;

    wmma::fragment<wmma::accumulator, 16, 16, 16, float> acc[FM][FN];
#pragma unroll
    for (int i = 0; i < FM; i++)
#pragma unroll
        for (int j = 0; j < FN; j++) wmma::fill_fragment(acc[i][j], 0.0f);

    auto issue_chunk = [&](int c) {
        const __half* __restrict__ srcX = (MODE == 0 && c >= 4) ? Agg : X;
        const int kcol = (MODE == 0) ? (c & 3) * 32 : c * 32;
        __half* xbuf = Xs + (c & 1) * BM * LDS;
        // 32 halves per row = 4 x 16B
#pragma unroll
        for (int i = tid; i < BM * 4; i += 256) {
            int m = i >> 2, kq = i & 3;
            int node = min(block_m + m, n_nodes - 1);
            cp16(&xbuf[m * LDS + kq * 8], srcX + (size_t)node * 128 + kcol + kq * 8);
        }
        __half* wbuf = Ws + (c & 1) * BN * LDS;
#pragma unroll
        for (int i = tid; i < BN * 4; i += 256) {
            int n = i >> 2, kq = i & 3;
            cp16(&wbuf[n * LDS + kq * 8], WT + (size_t)n * KTOTAL + c * 32 + kq * 8);
        }
        cp_commit();
    };

    issue_chunk(0);

    for (int c = 0; c < NCHUNK; ++c) {
        if (c + 1 < NCHUNK) {
            issue_chunk(c + 1);
            asm volatile("cp.async.wait_group 1;");
        } else {
            asm volatile("cp.async.wait_group 0;");
        }
        __syncthreads();

        const __half* xbuf = Xs + (c & 1) * BM * LDS;
        const __half* wbuf = Ws + (c & 1) * BN * LDS;

#pragma unroll
        for (int k0 = 0; k0 < 32; k0 += 16) {
            wmma::fragment<wmma::matrix_a, 16, 16, 16, __half, wmma::row_major> af[FM];
            wmma::fragment<wmma::matrix_b, 16, 16, 16, __half, wmma::col_major> bf[FN];
#pragma unroll
            for (int i = 0; i < FM; i++)
                wmma::load_matrix_sync(af[i], &xbuf[(wr * RM + i * 16) * LDS + k0], LDS);
#pragma unroll
            for (int j = 0; j < FN; j++)
                wmma::load_matrix_sync(bf[j], &wbuf[(wc * CN + j * 16) * LDS + k0], LDS);
#pragma unroll
            for (int i = 0; i < FM; i++)
#pragma unroll
                for (int j = 0; j < FN; j++)
                    wmma::mma_sync(acc[i][j], af[i], bf[j], acc[i][j]);
        }
        __syncthreads();
    }

    // Epilogue
    float* buf = &Sbuf[wid * 256];
#pragma unroll
    for (int i = 0; i < FM; i++) {
#pragma unroll
        for (int j = 0; j < FN; j++) {
            wmma::store_matrix_sync(buf, acc[i][j], 16, wmma::mem_row_major);
            __syncwarp();
            const int r = lane >> 1;
            const int c0 = (lane & 1) * 8;
            const int node = block_m + wr * RM + i * 16 + r;
            const int gcol = wc * CN + j * 16 + c0;
            if (node < n_nodes) {
#pragma unroll
                for (int q = 0; q < 8; q += 4) {
                    float4 v = *reinterpret_cast<const float4*>(&buf[r * 16 + c0 + q]);
                    int n = gcol + q;
                    if (MODE == 0) {
                        float4 bb = *reinterpret_cast<const float4*>(bias + n);
                        v.x = fmaxf(v.x + bb.x, 0.f);
                        v.y = fmaxf(v.y + bb.y, 0.f);
                        v.z = fmaxf(v.z + bb.z, 0.f);
                        v.w = fmaxf(v.w + bb.w, 0.f);
                        __half2 h01 = __floats2half2_rn(v.x, v.y);
                        __half2 h23 = __floats2half2_rn(v.z, v.w);
                        uint2 u;
                        u.x = *reinterpret_cast<uint32_t*>(&h01);
                        u.y = *reinterpret_cast<uint32_t*>(&h23);
                        *reinterpret_cast<uint2*>((__half*)out0 + (size_t)node * 128 + n) = u;
                    } else {
                        if (n < 64) {
                            __half2 h01 = __floats2half2_rn(v.x, v.y);
                            __half2 h23 = __floats2half2_rn(v.z, v.w);
                            uint2 u;
                            u.x = *reinterpret_cast<uint32_t*>(&h01);
                            u.y = *reinterpret_cast<uint32_t*>(&h23);
                            *reinterpret_cast<uint2*>((__half*)out0 + (size_t)node * 64 + n) = u;
                        } else {
                            int n2 = n - 64;
                            float4 bb = *reinterpret_cast<const float4*>(bias + n2);
                            v.x += bb.x; v.y += bb.y; v.z += bb.z; v.w += bb.w;
                            *reinterpret_cast<float4*>(out1 + (size_t)node * 64 + n2) = v;
                        }
                    }
                }
            }
            __syncwarp();
        }
    }
}

// ---------------------------------------------------------------------------
// Launch (single stream)
// ---------------------------------------------------------------------------
extern "C" void kernel_launch(void* const* d_in, const int* in_sizes, int n_in,
                              void* d_out, int out_size) {
    const float* features = (const float*)d_in[0];
    const int*   src      = (const int*)d_in[1];
    const int*   dst      = (const int*)d_in[2];
    const float* Wself0   = (const float*)d_in[3];
    const float* Wneigh0  = (const float*)d_in[4];
    const float* b0       = (const float*)d_in[5];
    const float* Wself1   = (const float*)d_in[6];
    const float* Wneigh1  = (const float*)d_in[7];
    const float* b1       = (const float*)d_in[8];

    const int n_nodes = in_sizes[0] / 128;
    const int n_edges = in_sizes[1];

    float *pout;
    __half *feat16, *agg0, *h16, *t16, *WT0, *WT1;
    int* cnt;
    cudaGetSymbolAddress((void**)&feat16, g_feat16);
    cudaGetSymbolAddress((void**)&agg0, g_agg0);
    cudaGetSymbolAddress((void**)&h16, g_h16);
    cudaGetSymbolAddress((void**)&t16, g_t16);
    cudaGetSymbolAddress((void**)&pout, g_pout);
    cudaGetSymbolAddress((void**)&WT0, g_WT0);
    cudaGetSymbolAddress((void**)&WT1, g_WT1);
    cudaGetSymbolAddress((void**)&cnt, g_cnt);

    const int smem_core = 40960;  // 2 CTAs/SM with room to spare
    static bool attr_set = false;
    if (!attr_set) {
        cudaFuncSetAttribute((const void*)gemm_core<256, 0>,
                             cudaFuncAttributeMaxDynamicSharedMemorySize, smem_core);
        cudaFuncSetAttribute((const void*)gemm_core<128, 1>,
                             cudaFuncAttributeMaxDynamicSharedMemorySize, smem_core);
        attr_set = true;
    }

    cudaMemsetAsync(cnt, 0, sizeof(int) * (size_t)n_nodes, 0);

    transpose_all<<<(24576 + 255) / 256, 256>>>(Wself0, Wneigh0, Wneigh1, Wself1);
    {
        int n8 = (n_nodes * 128) / 8;
        convert_feat<<<(n8 + 255) / 256, 256>>>(features, feat16, n8);
    }
    {
        int n4 = (n_edges + 3) / 4;
        fill_bucket<<<(n4 + 255) / 256, 256>>>(src, dst, n_edges);
    }

    const int gblocks = (n_nodes + 127) / 128;
    const int ablocks = (int)(((long long)n_nodes * 32 + 255) / 256);

    // mean-aggregate fp16 features -> agg0 (fp16, fp32 accum)
    agg128_kernel<<<ablocks, 256>>>(feat16, agg0, n_nodes);
    // h16 = relu(feat16@Ws0 + agg0@Wn0 + b0)
    gemm_core<256, 0><<<gblocks, 256, smem_core>>>(
        feat16, agg0, WT0, b0, h16, nullptr, n_nodes);
    // [t16 | pout] = h16 @ [Wn1 | Ws1] (+b1 on pout half)
    gemm_core<128, 1><<<gblocks, 256, smem_core>>>(
        h16, nullptr, WT1, b1, t16, pout, n_nodes);
    // out = pout + mean(t16[nbrs])
    agg64_final<<<ablocks, 256>>>(t16, pout, (float*)d_out, n_nodes);
}